// round 14
// baseline (speedup 1.0000x reference)
#include <cuda_runtime.h>
#include <cuda_fp16.h>
#include <cstdint>

// ---------------- scratch ----------------
__device__ __half g_xh[8192L * 768];
__device__ __half g_wth[3L * 768 * 768];   // W^T: [s][OUT][D] fp16
__device__ __half g_qh[8192L * 768];
__device__ __half g_kh[8192L * 768];
__device__ __half g_vth[4L * 768 * 2048];  // V^T per batch: [768][2048]
__device__ __half g_sp[4L * 2048 * 2048];  // fp16 scores, overwritten in place by P

// ---------------- helpers ----------------
__device__ __forceinline__ uint32_t smem_u32(const void* p) {
    uint32_t a;
    asm("{ .reg .u64 t; cvta.to.shared.u64 t, %1; cvt.u32.u64 %0, t; }" : "=r"(a) : "l"(p));
    return a;
}
__device__ __forceinline__ int flat_bid() {
    return (int)(blockIdx.z * gridDim.y * gridDim.x + blockIdx.y * gridDim.x + blockIdx.x);
}
#define LDSM_X4(R, addr) \
    asm volatile("ldmatrix.sync.aligned.m8n8.x4.shared.b16 {%0,%1,%2,%3}, [%4];" \
        : "=r"((R)[0]), "=r"((R)[1]), "=r"((R)[2]), "=r"((R)[3]) : "r"(addr))
#define MMA16816(C, A, B0, B1) \
    asm volatile("mma.sync.aligned.m16n8k16.row.col.f32.f16.f16.f32 " \
        "{%0,%1,%2,%3}, {%4,%5,%6,%7}, {%8,%9}, {%0,%1,%2,%3};" \
        : "+f"((C)[0]), "+f"((C)[1]), "+f"((C)[2]), "+f"((C)[3]) \
        : "r"((A)[0]), "r"((A)[1]), "r"((A)[2]), "r"((A)[3]), "r"(B0), "r"(B1))
#define REDADD_F32(ptr, val) \
    asm volatile("red.global.add.f32 [%0], %1;" :: "l"(ptr), "f"(val) : "memory")

// ---------------- tiling: CTA 128x128, warp grid 4(M)x2(N), warp tile 32x64 ----------------
#define TILE 128
#define BK 64
#define STAGES 3
#define OFF_A 0
#define OFF_B (16 * 1024)
#define STAGE_BYTES (32 * 1024)
#define SMEM_TOTAL (STAGES * STAGE_BYTES)   // 96 KB -> 2 CTAs/SM

__device__ __forceinline__ void load_tile_async(
    uint32_t s_base, const __half* __restrict__ g, long row0, int ld, int k0, int tid)
{
#pragma unroll
    for (int rep = 0; rep < 4; ++rep) {
        int i = tid + rep * 256;
        int r = i >> 3, c = i & 7;
        uint32_t sp = s_base + (uint32_t)(r * 128) + ((uint32_t)(c ^ (r & 7)) * 16);
        const void* gp = g + (row0 + r) * (long)ld + k0 + c * 8;
        asm volatile("cp.async.cg.shared.global [%0], [%1], 16;" :: "r"(sp), "l"(gp) : "memory");
    }
}

// c[i<2][j<8][4]; D[m,n] += A[m,k]*B[n,k], K-major operands, 3-stage pipeline.
// phase_it rotates the K-iteration start (wrapping) to de-phase co-resident CTAs.
__device__ __forceinline__ void gemm_mainloop(
    uint32_t sm, const __half* __restrict__ pA, const __half* __restrict__ pB,
    int K, int lda, int ldb, long bm, long bn, int tid, int phase_it, float (&c)[2][8][4])
{
    const int lane = tid & 31, wid = tid >> 5;
    const int wm = wid >> 1, wn = wid & 1;

    const int a_row = (lane & 7) + ((lane >> 3) & 1) * 8;
    const int a_kh  = lane >> 4;
    const int b_row = (lane & 7) + ((lane >> 4) & 1) * 8;
    const int b_kh  = (lane >> 3) & 1;

    const int iters = K / BK;

    int kload = phase_it;   // rotated k-iteration index for loads
#pragma unroll
    for (int s = 0; s < STAGES - 1; ++s) {
        const uint32_t sb = sm + s * STAGE_BYTES;
        load_tile_async(sb + OFF_A, pA, bm, lda, kload * BK, tid);
        load_tile_async(sb + OFF_B, pB, bn, ldb, kload * BK, tid);
        if (++kload == iters) kload = 0;
        asm volatile("cp.async.commit_group;" ::: "memory");
    }

    int st = 0, ld_st = STAGES - 1;
    for (int it = 0; it < iters; ++it) {
        asm volatile("cp.async.wait_group %0;" :: "n"(STAGES - 2) : "memory");
        __syncthreads();

        {
            if (it + STAGES - 1 < iters) {
                const uint32_t sq = sm + ld_st * STAGE_BYTES;
                load_tile_async(sq + OFF_A, pA, bm, lda, kload * BK, tid);
                load_tile_async(sq + OFF_B, pB, bn, ldb, kload * BK, tid);
                if (++kload == iters) kload = 0;
            }
            asm volatile("cp.async.commit_group;" ::: "memory");
            if (++ld_st == STAGES) ld_st = 0;
        }

        const uint32_t sb = sm + st * STAGE_BYTES;
        if (++st == STAGES) st = 0;
#pragma unroll
        for (int ks = 0; ks < 4; ++ks) {
            uint32_t ah[2][4], bb[8][2];
#pragma unroll
            for (int i = 0; i < 2; ++i) {
                int rg = wm * 32 + i * 16 + a_row;
                uint32_t off = (uint32_t)(rg * 128) +
                               ((uint32_t)((2 * ks + a_kh) ^ (rg & 7)) * 16);
                LDSM_X4(ah[i], sb + OFF_A + off);
            }
#pragma unroll
            for (int j2 = 0; j2 < 4; ++j2) {
                int rg = wn * 64 + j2 * 16 + b_row;
                uint32_t off = (uint32_t)(rg * 128) +
                               ((uint32_t)((2 * ks + b_kh) ^ (rg & 7)) * 16);
                uint32_t t[4];
                LDSM_X4(t, sb + OFF_B + off);
                bb[2 * j2][0] = t[0]; bb[2 * j2][1] = t[1];
                bb[2 * j2 + 1][0] = t[2]; bb[2 * j2 + 1][1] = t[3];
            }
#pragma unroll
            for (int i = 0; i < 2; ++i)
#pragma unroll
                for (int j = 0; j < 8; ++j)
                    MMA16816(c[i][j], ah[i], bb[j][0], bb[j][1]);
        }
    }
}

// ---------------- QKV kernel (merged, z selects output) ----------------
__global__ void __launch_bounds__(256, 2) qkv_gemm(
    const __half* __restrict__ xh, const __half* __restrict__ wth,
    __half* __restrict__ qh, __half* __restrict__ kh, __half* __restrict__ vth)
{
    extern __shared__ __align__(1024) char smem_raw[];
    const uint32_t sm = smem_u32(smem_raw);
    const int tid = threadIdx.x;
    const int lane = tid & 31, wid = tid >> 5;
    const int wm = wid >> 1, wn = wid & 1;
    const long bm = (long)blockIdx.y * TILE;
    const long bn = (long)blockIdx.x * TILE;
    const int z = blockIdx.z;
    const long WSL = 768L * 768;
    const int phase = ((flat_bid() / 148) & 1) * 6;   // iters=12

    float c[2][8][4];
#pragma unroll
    for (int i = 0; i < 2; i++)
#pragma unroll
        for (int j = 0; j < 8; j++)
#pragma unroll
            for (int e = 0; e < 4; e++) c[i][j][e] = 0.0f;

    gemm_mainloop(sm, xh, wth + z * WSL, 768, 768, 768, bm, bn, tid, phase, c);

    const int t4 = lane >> 2;
    const int t2 = (lane & 3) * 2;

    if (z < 2) {
        __half* hp = (z == 0) ? qh : kh;
#pragma unroll
        for (int i = 0; i < 2; ++i) {
            const long r0 = bm + wm * 32 + i * 16 + t4;
#pragma unroll
            for (int j = 0; j < 8; ++j) {
                const long col = bn + wn * 64 + j * 8 + t2;
#pragma unroll
                for (int h = 0; h < 2; ++h) {
                    const long r = r0 + 8 * h;
                    *reinterpret_cast<__half2*>(hp + r * 768 + col) = __halves2half2(
                        __float2half(c[i][j][2 * h]), __float2half(c[i][j][2 * h + 1]));
                }
            }
        }
    } else {
        // V^T: transpose via smem ([128 cols][132 rows] fp32), coalesced out
        float* smemT = reinterpret_cast<float*>(smem_raw);
        __syncthreads();
#pragma unroll
        for (int i = 0; i < 2; ++i) {
            const int rl0 = wm * 32 + i * 16 + t4;
#pragma unroll
            for (int j = 0; j < 8; ++j) {
                const int cl = wn * 64 + j * 8 + t2;
#pragma unroll
                for (int h = 0; h < 2; ++h) {
                    smemT[(cl + 0) * 132 + rl0 + 8 * h] = c[i][j][2 * h + 0];
                    smemT[(cl + 1) * 132 + rl0 + 8 * h] = c[i][j][2 * h + 1];
                }
            }
        }
        __syncthreads();
        const long batch = bm >> 11, mbase = bm & 2047;
#pragma unroll
        for (int rep = 0; rep < 16; ++rep) {
            const int idx = tid + rep * 256;
            const int nl = idx >> 5, m4 = (idx & 31) * 4;
            float4 v = *reinterpret_cast<float4*>(&smemT[nl * 132 + m4]);
            const long o = (batch * 768 + bn + nl) * 2048 + mbase + m4;
            *reinterpret_cast<__half2*>(vth + o) =
                __halves2half2(__float2half(v.x), __float2half(v.y));
            *reinterpret_cast<__half2*>(vth + o + 2) =
                __halves2half2(__float2half(v.z), __float2half(v.w));
        }
    }
}

// ---------------- scores GEMM: fp16 out, /8 folded ----------------
__global__ void __launch_bounds__(256, 2) gemm_scores(
    const __half* __restrict__ A, const __half* __restrict__ B, __half* __restrict__ Ch)
{
    extern __shared__ __align__(1024) char smem_raw[];
    const uint32_t sm = smem_u32(smem_raw);
    const int tid = threadIdx.x;
    const int lane = tid & 31, wid = tid >> 5;
    const int wm = wid >> 1, wn = wid & 1;
    const long bm = (long)blockIdx.y * TILE;
    const long bn = (long)blockIdx.x * TILE;
    const int b = blockIdx.z;
    const int phase = ((flat_bid() / 148) & 1) * 6;   // iters=12

    const __half* pA = A + b * (2048L * 768);
    const __half* pB = B + b * (2048L * 768);

    float c[2][8][4];
#pragma unroll
    for (int i = 0; i < 2; i++)
#pragma unroll
        for (int j = 0; j < 8; j++)
#pragma unroll
            for (int e = 0; e < 4; e++) c[i][j][e] = 0.0f;

    gemm_mainloop(sm, pA, pB, 768, 768, 768, bm, bn, tid, phase, c);

    const int t4 = lane >> 2;
    const int t2 = (lane & 3) * 2;
    __half* base = Ch + b * (2048L * 2048);
#pragma unroll
    for (int i = 0; i < 2; ++i) {
        const long r0 = bm + wm * 32 + i * 16 + t4;
#pragma unroll
        for (int j = 0; j < 8; ++j) {
            const long col = bn + wn * 64 + j * 8 + t2;
#pragma unroll
            for (int h = 0; h < 2; ++h) {
                const long r = r0 + 8 * h;
                *reinterpret_cast<__half2*>(base + r * 2048 + col) = __halves2half2(
                    __float2half(0.125f * c[i][j][2 * h]),
                    __float2half(0.125f * c[i][j][2 * h + 1]));
            }
        }
    }
}

// ---------------- PV GEMM, split-K=2, RED-atomic accumulate to out ----------------
__global__ void __launch_bounds__(256, 2) gemm_pv(
    const __half* __restrict__ A, const __half* __restrict__ B, float* __restrict__ out)
{
    extern __shared__ __align__(1024) char smem_raw[];
    const uint32_t sm = smem_u32(smem_raw);
    const int tid = threadIdx.x;
    const int lane = tid & 31, wid = tid >> 5;
    const int wm = wid >> 1, wn = wid & 1;
    const long bm = (long)blockIdx.y * TILE;
    const long bn = (long)blockIdx.x * TILE;
    const int b = blockIdx.z >> 1;
    const int kh = blockIdx.z & 1;
    const int phase = ((flat_bid() / 148) & 1) * 8;   // iters=16

    const __half* pA = A + b * (2048L * 2048) + kh * 1024;
    const __half* pB = B + b * (768L * 2048) + kh * 1024;

    float c[2][8][4];
#pragma unroll
    for (int i = 0; i < 2; i++)
#pragma unroll
        for (int j = 0; j < 8; j++)
#pragma unroll
            for (int e = 0; e < 4; e++) c[i][j][e] = 0.0f;

    gemm_mainloop(sm, pA, pB, 1024, 2048, 2048, bm, bn, tid, phase, c);

    const int t4 = lane >> 2;
    const int t2 = (lane & 3) * 2;
    float* q = out + b * (2048L * 768);
#pragma unroll
    for (int i = 0; i < 2; ++i) {
        const long r0 = bm + wm * 32 + i * 16 + t4;
#pragma unroll
        for (int j = 0; j < 8; ++j) {
            const long col = bn + wn * 64 + j * 8 + t2;
#pragma unroll
            for (int h = 0; h < 2; ++h) {
                const long r = r0 + 8 * h;
                float* p0 = q + r * 768 + col;
                REDADD_F32(p0,     c[i][j][2 * h]);
                REDADD_F32(p0 + 1, c[i][j][2 * h + 1]);
            }
        }
    }
}

// ---------------- merged split (x -> fp16, W -> W^T fp16, zero out) ----------------
__global__ void split_all_kernel(const float* __restrict__ x, const float* __restrict__ w,
                                 __half* __restrict__ xh, __half* __restrict__ wth,
                                 float* __restrict__ outz)
{
    const long N1 = 8192L * 768;
    const long N2 = 3L * 768 * 768;
    const long NOUT = 4L * 2048 * 768;
    long i = (long)blockIdx.x * blockDim.x + threadIdx.x;
    if (i < NOUT) outz[i] = 0.0f;
    if (i < N1) {
        xh[i] = __float2half(x[i]);
    } else if (i < N1 + N2) {
        long j = i - N1;
        long s = j / (768 * 768), r = j % (768 * 768);
        long o = r / 768, d = r % 768;
        wth[j] = __float2half(w[s * 768 * 768 + d * 768 + o]);
    }
}

// ---------------- in-place softmax over fp16 rows of 2048 ----------------
__global__ __launch_bounds__(256) void softmax_kernel(__half* __restrict__ S)
{
    const long row = blockIdx.x;
    __half* p = S + row * 2048;
    const int tid = threadIdx.x;

    uint4 raw = reinterpret_cast<const uint4*>(p)[tid];
    __half2 hv[4];
    hv[0] = *reinterpret_cast<__half2*>(&raw.x);
    hv[1] = *reinterpret_cast<__half2*>(&raw.y);
    hv[2] = *reinterpret_cast<__half2*>(&raw.z);
    hv[3] = *reinterpret_cast<__half2*>(&raw.w);

    float local[8];
    float mx = -1e30f;
#pragma unroll
    for (int r = 0; r < 4; r++) {
        float2 f = __half22float2(hv[r]);
        local[2 * r] = f.x; local[2 * r + 1] = f.y;
        mx = fmaxf(mx, fmaxf(f.x, f.y));
    }

    __shared__ float red[32];
#pragma unroll
    for (int o = 16; o; o >>= 1) mx = fmaxf(mx, __shfl_xor_sync(0xffffffffu, mx, o));
    if ((tid & 31) == 0) red[tid >> 5] = mx;
    __syncthreads();
    if (tid < 32) {
        float v = (tid < 8) ? red[tid] : -1e30f;
#pragma unroll
        for (int o = 4; o; o >>= 1) v = fmaxf(v, __shfl_xor_sync(0xffffffffu, v, o));
        red[tid] = v;
    }
    __syncthreads();
    mx = red[0];

    float s = 0.0f;
#pragma unroll
    for (int r = 0; r < 8; r++) { local[r] = __expf(local[r] - mx); s += local[r]; }
    __shared__ float red2[32];
#pragma unroll
    for (int o = 16; o; o >>= 1) s += __shfl_xor_sync(0xffffffffu, s, o);
    if ((tid & 31) == 0) red2[tid >> 5] = s;
    __syncthreads();
    if (tid < 32) {
        float v = (tid < 8) ? red2[tid] : 0.0f;
#pragma unroll
        for (int o = 4; o; o >>= 1) v += __shfl_xor_sync(0xffffffffu, v, o);
        red2[tid] = v;
    }
    __syncthreads();
    const float inv = 1.0f / red2[0];

    uint4 outv;
    __half2* ov = reinterpret_cast<__half2*>(&outv);
#pragma unroll
    for (int r = 0; r < 4; r++)
        ov[r] = __halves2half2(__float2half(local[2 * r] * inv),
                               __float2half(local[2 * r + 1] * inv));
    reinterpret_cast<uint4*>(p)[tid] = outv;
}

// ---------------- host ----------------
extern "C" void kernel_launch(void* const* d_in, const int* in_sizes, int n_in,
                              void* d_out, int out_size)
{
    const float* x = (const float*)d_in[0];   // [4,2048,768]
    const float* w = (const float*)d_in[1];   // [3,768,768]
    float* out = (float*)d_out;               // [4,2048,768]

    __half *xh, *wth, *qh, *kh, *vth, *sp;
    cudaGetSymbolAddress((void**)&xh, g_xh);
    cudaGetSymbolAddress((void**)&wth, g_wth);
    cudaGetSymbolAddress((void**)&qh, g_qh);
    cudaGetSymbolAddress((void**)&kh, g_kh);
    cudaGetSymbolAddress((void**)&vth, g_vth);
    cudaGetSymbolAddress((void**)&sp, g_sp);

    cudaFuncSetAttribute(qkv_gemm, cudaFuncAttributeMaxDynamicSharedMemorySize, SMEM_TOTAL);
    cudaFuncSetAttribute(gemm_scores, cudaFuncAttributeMaxDynamicSharedMemorySize, SMEM_TOTAL);
    cudaFuncSetAttribute(gemm_pv, cudaFuncAttributeMaxDynamicSharedMemorySize, SMEM_TOTAL);

    const long NSPLIT = 8192L * 768 + 3L * 768 * 768;
    split_all_kernel<<<(int)((NSPLIT + 1023) / 1024), 1024>>>(x, w, xh, wth, out);

    // QKV: M=8192, N=768, K=768, z = {Q, K, V}
    qkv_gemm<<<dim3(6, 64, 3), 256, SMEM_TOTAL>>>(xh, wth, qh, kh, vth);

    // scores = Q K^T / 8 : per batch M=2048, N=2048, K=768 -> fp16
    gemm_scores<<<dim3(16, 16, 4), 256, SMEM_TOTAL>>>(qh, kh, sp);

    // softmax in place (fp16 scores -> fp16 P)
    softmax_kernel<<<8192, 256>>>(sp);

    // out = P V, split-K=2, RED accumulate: z = batch*2 + khalf
    gemm_pv<<<dim3(6, 16, 8), 256, SMEM_TOTAL>>>(sp, vth, out);
}

// round 17
// speedup vs baseline: 1.0629x; 1.0629x over previous
#include <cuda_runtime.h>
#include <cuda_fp16.h>
#include <cstdint>

// ---------------- scratch ----------------
__device__ __half g_xh[8192L * 768];
__device__ __half g_wth[3L * 768 * 768];   // W^T: [s][OUT][D] fp16
__device__ __half g_qh[8192L * 768];
__device__ __half g_kh[8192L * 768];
__device__ __half g_vth[4L * 768 * 2048];  // V^T per batch: [768][2048]
__device__ __half g_sp[4L * 2048 * 2048];  // unnormalized exp-scores (fp16)
__device__ float g_partsum[8192L * 16];    // per-row, per-bn-tile partial exp sums

// ---------------- helpers ----------------
__device__ __forceinline__ uint32_t smem_u32(const void* p) {
    uint32_t a;
    asm("{ .reg .u64 t; cvta.to.shared.u64 t, %1; cvt.u32.u64 %0, t; }" : "=r"(a) : "l"(p));
    return a;
}
#define LDSM_X4(R, addr) \
    asm volatile("ldmatrix.sync.aligned.m8n8.x4.shared.b16 {%0,%1,%2,%3}, [%4];" \
        : "=r"((R)[0]), "=r"((R)[1]), "=r"((R)[2]), "=r"((R)[3]) : "r"(addr))
#define MMA16816(C, A, B0, B1) \
    asm volatile("mma.sync.aligned.m16n8k16.row.col.f32.f16.f16.f32 " \
        "{%0,%1,%2,%3}, {%4,%5,%6,%7}, {%8,%9}, {%0,%1,%2,%3};" \
        : "+f"((C)[0]), "+f"((C)[1]), "+f"((C)[2]), "+f"((C)[3]) \
        : "r"((A)[0]), "r"((A)[1]), "r"((A)[2]), "r"((A)[3]), "r"(B0), "r"(B1))
#define REDADD_F32(ptr, val) \
    asm volatile("red.global.add.f32 [%0], %1;" :: "l"(ptr), "f"(val) : "memory")

// ---------------- tiling: CTA 128x128, warp grid 4(M)x2(N), warp tile 32x64 ----------------
#define TILE 128
#define BK 64
#define STAGES 3
#define OFF_A 0
#define OFF_B (16 * 1024)
#define STAGE_BYTES (32 * 1024)
#define OFF_AUX (STAGES * STAGE_BYTES)           // 1.25 KB aux region after stages
#define SMEM_TOTAL (STAGES * STAGE_BYTES + 1280) // 97.25 KB -> still 2 CTAs/SM

__device__ __forceinline__ void load_tile_async(
    uint32_t s_base, const __half* __restrict__ g, long row0, int ld, int k0, int tid)
{
#pragma unroll
    for (int rep = 0; rep < 4; ++rep) {
        int i = tid + rep * 256;
        int r = i >> 3, c = i & 7;
        uint32_t sp = s_base + (uint32_t)(r * 128) + ((uint32_t)(c ^ (r & 7)) * 16);
        const void* gp = g + (row0 + r) * (long)ld + k0 + c * 8;
        asm volatile("cp.async.cg.shared.global [%0], [%1], 16;" :: "r"(sp), "l"(gp) : "memory");
    }
}

// c[i<2][j<8][4]; D[m,n] += A[m,k]*B[n,k], K-major operands, 3-stage pipeline.
__device__ __forceinline__ void gemm_mainloop(
    uint32_t sm, const __half* __restrict__ pA, const __half* __restrict__ pB,
    int K, int lda, int ldb, long bm, long bn, int tid, float (&c)[2][8][4])
{
    const int lane = tid & 31, wid = tid >> 5;
    const int wm = wid >> 1, wn = wid & 1;

    const int a_row = (lane & 7) + ((lane >> 3) & 1) * 8;
    const int a_kh  = lane >> 4;
    const int b_row = (lane & 7) + ((lane >> 4) & 1) * 8;
    const int b_kh  = (lane >> 3) & 1;

    const int iters = K / BK;

#pragma unroll
    for (int s = 0; s < STAGES - 1; ++s) {
        if (s < iters) {
            const uint32_t sb = sm + s * STAGE_BYTES;
            load_tile_async(sb + OFF_A, pA, bm, lda, s * BK, tid);
            load_tile_async(sb + OFF_B, pB, bn, ldb, s * BK, tid);
        }
        asm volatile("cp.async.commit_group;" ::: "memory");
    }

    int st = 0, ld_st = STAGES - 1;
    for (int it = 0; it < iters; ++it) {
        asm volatile("cp.async.wait_group %0;" :: "n"(STAGES - 2) : "memory");
        __syncthreads();

        {
            const int ld_it = it + STAGES - 1;
            if (ld_it < iters) {
                const uint32_t sq = sm + ld_st * STAGE_BYTES;
                load_tile_async(sq + OFF_A, pA, bm, lda, ld_it * BK, tid);
                load_tile_async(sq + OFF_B, pB, bn, ldb, ld_it * BK, tid);
            }
            asm volatile("cp.async.commit_group;" ::: "memory");
            if (++ld_st == STAGES) ld_st = 0;
        }

        const uint32_t sb = sm + st * STAGE_BYTES;
        if (++st == STAGES) st = 0;
#pragma unroll
        for (int ks = 0; ks < 4; ++ks) {
            uint32_t ah[2][4], bb[8][2];
#pragma unroll
            for (int i = 0; i < 2; ++i) {
                int rg = wm * 32 + i * 16 + a_row;
                uint32_t off = (uint32_t)(rg * 128) +
                               ((uint32_t)((2 * ks + a_kh) ^ (rg & 7)) * 16);
                LDSM_X4(ah[i], sb + OFF_A + off);
            }
#pragma unroll
            for (int j2 = 0; j2 < 4; ++j2) {
                int rg = wn * 64 + j2 * 16 + b_row;
                uint32_t off = (uint32_t)(rg * 128) +
                               ((uint32_t)((2 * ks + b_kh) ^ (rg & 7)) * 16);
                uint32_t t[4];
                LDSM_X4(t, sb + OFF_B + off);
                bb[2 * j2][0] = t[0]; bb[2 * j2][1] = t[1];
                bb[2 * j2 + 1][0] = t[2]; bb[2 * j2 + 1][1] = t[3];
            }
#pragma unroll
            for (int i = 0; i < 2; ++i)
#pragma unroll
                for (int j = 0; j < 8; ++j)
                    MMA16816(c[i][j], ah[i], bb[j][0], bb[j][1]);
        }
    }
}

// ---------------- QKV kernel (merged, z selects output) ----------------
__global__ void __launch_bounds__(256, 2) qkv_gemm(
    const __half* __restrict__ xh, const __half* __restrict__ wth,
    __half* __restrict__ qh, __half* __restrict__ kh, __half* __restrict__ vth)
{
    extern __shared__ __align__(1024) char smem_raw[];
    const uint32_t sm = smem_u32(smem_raw);
    const int tid = threadIdx.x;
    const int lane = tid & 31, wid = tid >> 5;
    const int wm = wid >> 1, wn = wid & 1;
    const long bm = (long)blockIdx.y * TILE;
    const long bn = (long)blockIdx.x * TILE;
    const int z = blockIdx.z;
    const long WSL = 768L * 768;

    float c[2][8][4];
#pragma unroll
    for (int i = 0; i < 2; i++)
#pragma unroll
        for (int j = 0; j < 8; j++)
#pragma unroll
            for (int e = 0; e < 4; e++) c[i][j][e] = 0.0f;

    gemm_mainloop(sm, xh, wth + z * WSL, 768, 768, 768, bm, bn, tid, c);

    const int t4 = lane >> 2;
    const int t2 = (lane & 3) * 2;

    if (z < 2) {
        __half* hp = (z == 0) ? qh : kh;
#pragma unroll
        for (int i = 0; i < 2; ++i) {
            const long r0 = bm + wm * 32 + i * 16 + t4;
#pragma unroll
            for (int j = 0; j < 8; ++j) {
                const long col = bn + wn * 64 + j * 8 + t2;
#pragma unroll
                for (int h = 0; h < 2; ++h) {
                    const long r = r0 + 8 * h;
                    *reinterpret_cast<__half2*>(hp + r * 768 + col) = __halves2half2(
                        __float2half(c[i][j][2 * h]), __float2half(c[i][j][2 * h + 1]));
                }
            }
        }
    } else {
        // V^T: transpose via smem ([128 cols][132 rows] fp32), coalesced out
        float* smemT = reinterpret_cast<float*>(smem_raw);
        __syncthreads();
#pragma unroll
        for (int i = 0; i < 2; ++i) {
            const int rl0 = wm * 32 + i * 16 + t4;
#pragma unroll
            for (int j = 0; j < 8; ++j) {
                const int cl = wn * 64 + j * 8 + t2;
#pragma unroll
                for (int h = 0; h < 2; ++h) {
                    smemT[(cl + 0) * 132 + rl0 + 8 * h] = c[i][j][2 * h + 0];
                    smemT[(cl + 1) * 132 + rl0 + 8 * h] = c[i][j][2 * h + 1];
                }
            }
        }
        __syncthreads();
        const long batch = bm >> 11, mbase = bm & 2047;
#pragma unroll
        for (int rep = 0; rep < 16; ++rep) {
            const int idx = tid + rep * 256;
            const int nl = idx >> 5, m4 = (idx & 31) * 4;
            float4 v = *reinterpret_cast<float4*>(&smemT[nl * 132 + m4]);
            const long o = (batch * 768 + bn + nl) * 2048 + mbase + m4;
            *reinterpret_cast<__half2*>(vth + o) =
                __halves2half2(__float2half(v.x), __float2half(v.y));
            *reinterpret_cast<__half2*>(vth + o + 2) =
                __halves2half2(__float2half(v.z), __float2half(v.w));
        }
    }
}

// ---------------- scores GEMM: expS = exp(s/8 - 4) fp16 + per-row partial sums ----------------
__global__ void __launch_bounds__(256, 2) gemm_scores(
    const __half* __restrict__ A, const __half* __restrict__ B,
    __half* __restrict__ Ch, float* __restrict__ partsum)
{
    extern __shared__ __align__(1024) char smem_raw[];
    const uint32_t sm = smem_u32(smem_raw);
    const int tid = threadIdx.x;
    const int lane = tid & 31, wid = tid >> 5;
    const int wm = wid >> 1, wn = wid & 1;
    const long bm = (long)blockIdx.y * TILE;
    const long bn = (long)blockIdx.x * TILE;
    const int b = blockIdx.z;

    const __half* pA = A + b * (2048L * 768);
    const __half* pB = B + b * (2048L * 768);

    float c[2][8][4];
#pragma unroll
    for (int i = 0; i < 2; i++)
#pragma unroll
        for (int j = 0; j < 8; j++)
#pragma unroll
            for (int e = 0; e < 4; e++) c[i][j][e] = 0.0f;

    gemm_mainloop(sm, pA, pB, 768, 768, 768, bm, bn, tid, c);

    const int t4 = lane >> 2;
    const int t2 = (lane & 3) * 2;
    __half* base = Ch + b * (2048L * 2048);
    float* rowpart = reinterpret_cast<float*>(smem_raw + OFF_AUX);  // [2][128]

    float rsum[2][2];  // per (i, h) row partial over this thread's 16 columns
#pragma unroll
    for (int i = 0; i < 2; ++i) {
        const long r0 = bm + wm * 32 + i * 16 + t4;
#pragma unroll
        for (int h = 0; h < 2; ++h) rsum[i][h] = 0.0f;
#pragma unroll
        for (int j = 0; j < 8; ++j) {
            const long col = bn + wn * 64 + j * 8 + t2;
#pragma unroll
            for (int h = 0; h < 2; ++h) {
                const long r = r0 + 8 * h;
                const float ea = __expf(0.125f * c[i][j][2 * h]     - 4.0f);
                const float eb = __expf(0.125f * c[i][j][2 * h + 1] - 4.0f);
                rsum[i][h] += ea + eb;
                *reinterpret_cast<__half2*>(base + r * 2048 + col) =
                    __halves2half2(__float2half(ea), __float2half(eb));
            }
        }
    }
    // reduce across the 4 lanes (t2 groups) sharing each row — fixed order
#pragma unroll
    for (int i = 0; i < 2; ++i)
#pragma unroll
        for (int h = 0; h < 2; ++h) {
            rsum[i][h] += __shfl_xor_sync(0xffffffffu, rsum[i][h], 1);
            rsum[i][h] += __shfl_xor_sync(0xffffffffu, rsum[i][h], 2);
        }
    __syncthreads();   // stages dead; reuse aux smem
    if ((lane & 3) == 0) {
#pragma unroll
        for (int i = 0; i < 2; ++i)
#pragma unroll
            for (int h = 0; h < 2; ++h)
                rowpart[wn * 128 + wm * 32 + i * 16 + t4 + 8 * h] = rsum[i][h];
    }
    __syncthreads();
    if (tid < 128) {
        const long grow = b * 2048L + bm + tid;
        partsum[grow * 16 + blockIdx.x] = rowpart[tid] + rowpart[128 + tid];
    }
}

// ---------------- PV GEMM, split-K=2, normalize by rowsum, RED accumulate ----------------
__global__ void __launch_bounds__(256, 2) gemm_pv(
    const __half* __restrict__ A, const __half* __restrict__ B,
    const float* __restrict__ partsum, float* __restrict__ out)
{
    extern __shared__ __align__(1024) char smem_raw[];
    const uint32_t sm = smem_u32(smem_raw);
    const int tid = threadIdx.x;
    const int lane = tid & 31, wid = tid >> 5;
    const int wm = wid >> 1, wn = wid & 1;
    const long bm = (long)blockIdx.y * TILE;
    const long bn = (long)blockIdx.x * TILE;
    const int b = blockIdx.z >> 1;
    const int kh = blockIdx.z & 1;

    // prologue: deterministic per-row inverse sums into aux smem (fixed-order adds)
    float* rinv = reinterpret_cast<float*>(smem_raw + OFF_AUX);  // [128]
    if (tid < 128) {
        const long grow = b * 2048L + bm + tid;
        float s = 0.0f;
#pragma unroll
        for (int t = 0; t < 16; ++t) s += partsum[grow * 16 + t];
        rinv[tid] = 1.0f / s;
    }

    const __half* pA = A + b * (2048L * 2048) + kh * 1024;
    const __half* pB = B + b * (768L * 2048) + kh * 1024;

    float c[2][8][4];
#pragma unroll
    for (int i = 0; i < 2; i++)
#pragma unroll
        for (int j = 0; j < 8; j++)
#pragma unroll
            for (int e = 0; e < 4; e++) c[i][j][e] = 0.0f;

    gemm_mainloop(sm, pA, pB, 1024, 2048, 2048, bm, bn, tid, c);
    // mainloop's internal __syncthreads() make rinv[] visible; aux region untouched by stages

    const int t4 = lane >> 2;
    const int t2 = (lane & 3) * 2;
    float* q = out + b * (2048L * 768);
#pragma unroll
    for (int i = 0; i < 2; ++i) {
        const int rl0 = wm * 32 + i * 16 + t4;
#pragma unroll
        for (int j = 0; j < 8; ++j) {
            const long col = bn + wn * 64 + j * 8 + t2;
#pragma unroll
            for (int h = 0; h < 2; ++h) {
                const int rl = rl0 + 8 * h;
                const float inv = rinv[rl];
                float* p0 = q + (bm + rl) * 768 + col;
                REDADD_F32(p0,     c[i][j][2 * h]     * inv);
                REDADD_F32(p0 + 1, c[i][j][2 * h + 1] * inv);
            }
        }
    }
}

// ---------------- merged split (x -> fp16, W -> W^T fp16, zero out) ----------------
__global__ void split_all_kernel(const float* __restrict__ x, const float* __restrict__ w,
                                 __half* __restrict__ xh, __half* __restrict__ wth,
                                 float* __restrict__ outz)
{
    const long N1 = 8192L * 768;
    const long N2 = 3L * 768 * 768;
    const long NOUT = 4L * 2048 * 768;
    long i = (long)blockIdx.x * blockDim.x + threadIdx.x;
    if (i < NOUT) outz[i] = 0.0f;
    if (i < N1) {
        xh[i] = __float2half(x[i]);
    } else if (i < N1 + N2) {
        long j = i - N1;
        long s = j / (768 * 768), r = j % (768 * 768);
        long o = r / 768, d = r % 768;
        wth[j] = __float2half(w[s * 768 * 768 + d * 768 + o]);
    }
}

// ---------------- host ----------------
extern "C" void kernel_launch(void* const* d_in, const int* in_sizes, int n_in,
                              void* d_out, int out_size)
{
    const float* x = (const float*)d_in[0];   // [4,2048,768]
    const float* w = (const float*)d_in[1];   // [3,768,768]
    float* out = (float*)d_out;               // [4,2048,768]

    __half *xh, *wth, *qh, *kh, *vth, *sp;
    float* ps;
    cudaGetSymbolAddress((void**)&xh, g_xh);
    cudaGetSymbolAddress((void**)&wth, g_wth);
    cudaGetSymbolAddress((void**)&qh, g_qh);
    cudaGetSymbolAddress((void**)&kh, g_kh);
    cudaGetSymbolAddress((void**)&vth, g_vth);
    cudaGetSymbolAddress((void**)&sp, g_sp);
    cudaGetSymbolAddress((void**)&ps, g_partsum);

    cudaFuncSetAttribute(qkv_gemm, cudaFuncAttributeMaxDynamicSharedMemorySize, SMEM_TOTAL);
    cudaFuncSetAttribute(gemm_scores, cudaFuncAttributeMaxDynamicSharedMemorySize, SMEM_TOTAL);
    cudaFuncSetAttribute(gemm_pv, cudaFuncAttributeMaxDynamicSharedMemorySize, SMEM_TOTAL);

    const long NSPLIT = 8192L * 768 + 3L * 768 * 768;
    split_all_kernel<<<(int)((NSPLIT + 1023) / 1024), 1024>>>(x, w, xh, wth, out);

    // QKV: M=8192, N=768, K=768, z = {Q, K, V}
    qkv_gemm<<<dim3(6, 64, 3), 256, SMEM_TOTAL>>>(xh, wth, qh, kh, vth);

    // expS = exp(Q K^T / 8 - 4) (fp16) + per-row partial sums
    gemm_scores<<<dim3(16, 16, 4), 256, SMEM_TOTAL>>>(qh, kh, sp, ps);

    // out = (expS V) / rowsum, split-K=2, RED accumulate: z = batch*2 + khalf
    gemm_pv<<<dim3(6, 16, 8), 256, SMEM_TOTAL>>>(sp, vth, ps, out);
}